// round 11
// baseline (speedup 1.0000x reference)
#include <cuda_runtime.h>
#include <cuda_bf16.h>
#include <cstdint>

#define NB 16
#define NT 2048
#define NV 512
#define BM 128
#define BN 128
#define BK 32    // bf16 elements per k-tile
#define NCH 16
#define CHW (NT / NCH)  // 128

// Scratch (allocation-free rule: __device__ globals).
__device__ __nv_bfloat16 g_A[(size_t)NB * NT * NV];   // L1, then reused as S
__device__ float g_KT[(size_t)NB * NV * NT];          // K transposed per batch
__device__ __nv_bfloat16 g_WqT[NV * NV];              // Wq^T in bf16, [n][k]
__device__ __nv_bfloat16 g_WvR[NV * NV];              // Wv in bf16, [n][k]
__device__ unsigned short g_pos[NB * NT];             // CSR positions (sorted)
__device__ int g_off[NB * (NV + 1)];                  // CSR offsets
__device__ int g_cnt[NB * NCH * NV];                  // per-chunk counts
__device__ int g_off2[NB * NCH * NV];                 // per-chunk start offsets

__device__ __forceinline__ uint32_t smem_u32(const void* p) {
    return (uint32_t)__cvta_generic_to_shared(p);
}

// ---------------------------------------------------------------------------
// Wq transpose (512x512) -> bf16, [n][k] layout
// ---------------------------------------------------------------------------
__global__ void k_wqt(const float* __restrict__ W, __nv_bfloat16* __restrict__ WT) {
    __shared__ float t[32][33];
    int x = blockIdx.x * 32 + threadIdx.x;
    int y = blockIdx.y * 32 + threadIdx.y;
#pragma unroll
    for (int j = 0; j < 32; j += 8)
        t[threadIdx.y + j][threadIdx.x] = W[(size_t)(y + j) * NV + x];
    __syncthreads();
    x = blockIdx.y * 32 + threadIdx.x;
    y = blockIdx.x * 32 + threadIdx.y;
#pragma unroll
    for (int j = 0; j < 32; j += 8)
        WT[(size_t)(y + j) * NV + x] = __float2bfloat16(t[threadIdx.x][threadIdx.y + j]);
}

// ---------------------------------------------------------------------------
// Wv -> bf16 copy
// ---------------------------------------------------------------------------
__global__ void k_wv(const float* __restrict__ src, __nv_bfloat16* __restrict__ dst) {
    int i4 = (blockIdx.x * 256 + threadIdx.x) * 4;
    float4 v = *(const float4*)(src + i4);
    __nv_bfloat162* d2 = (__nv_bfloat162*)(dst + i4);
    d2[0] = __floats2bfloat162_rn(v.x, v.y);
    d2[1] = __floats2bfloat162_rn(v.z, v.w);
}

// ---------------------------------------------------------------------------
// Parallel CSR build: hist (per 128-token chunk) -> scan -> fill
// ---------------------------------------------------------------------------
__global__ void k_hist(const int* __restrict__ idx, int* __restrict__ cnt) {
    const int c = blockIdx.x, b = blockIdx.y, v = threadIdx.x;
    __shared__ int sidx[CHW];
    if (v < CHW) sidx[v] = idx[b * NT + c * CHW + v];
    __syncthreads();
    int n = 0;
#pragma unroll 8
    for (int r = 0; r < CHW; r++) n += (sidx[r] == v);
    cnt[(b * NCH + c) * NV + v] = n;
}

__global__ void k_scan(const int* __restrict__ cnt, int* __restrict__ off,
                       int* __restrict__ off2) {
    const int b = blockIdx.x, v = threadIdx.x;
    __shared__ int wsum[16];
    int c[NCH];
    int tot = 0;
#pragma unroll
    for (int j = 0; j < NCH; j++) {
        c[j] = cnt[(b * NCH + j) * NV + v];
        tot += c[j];
    }
    const int lane = v & 31, w = v >> 5;
    int incl = tot;
#pragma unroll
    for (int d = 1; d < 32; d <<= 1) {
        int x = __shfl_up_sync(0xffffffffu, incl, d);
        if (lane >= d) incl += x;
    }
    if (lane == 31) wsum[w] = incl;
    __syncthreads();
    if (w == 0) {
        int s = (lane < 16) ? wsum[lane] : 0;
#pragma unroll
        for (int d = 1; d < 16; d <<= 1) {
            int x = __shfl_up_sync(0xffffffffu, s, d);
            if (lane >= d) s += x;
        }
        if (lane < 16) wsum[lane] = s;
    }
    __syncthreads();
    int o = incl - tot + (w ? wsum[w - 1] : 0);  // exclusive prefix
    off[b * (NV + 1) + v] = o;
    if (v == NV - 1) off[b * (NV + 1) + NV] = NT;
#pragma unroll
    for (int j = 0; j < NCH; j++) {
        off2[(b * NCH + j) * NV + v] = o;
        o += c[j];
    }
}

__global__ void k_fill(const int* __restrict__ idx, const int* __restrict__ off2,
                       unsigned short* __restrict__ pos) {
    const int c = blockIdx.x, b = blockIdx.y, v = threadIdx.x;
    __shared__ int sidx[CHW];
    if (v < CHW) sidx[v] = idx[b * NT + c * CHW + v];
    __syncthreads();
    int o = off2[(b * NCH + c) * NV + v];
    for (int r = 0; r < CHW; r++)
        if (sidx[r] == v) pos[b * NT + (o++)] = (unsigned short)(c * CHW + r);
}

// ---------------------------------------------------------------------------
// L1[b,s,v] = sum_{r<=s, idx[b,r]==v} pt[s-r], atomic-free via CSR.
// 256 threads; thread owns v0=2*tid, v1=2*tid+1; packed bf16x2 u32 stores.
// ---------------------------------------------------------------------------
__global__ void __launch_bounds__(256)
k_build_l1(const unsigned short* __restrict__ pos, const int* __restrict__ off,
           const float* __restrict__ pt, __nv_bfloat16* __restrict__ L1) {
    const int s0 = blockIdx.x * 32, b = blockIdx.y;
    const int tid = threadIdx.x;
    const int smax = s0 + 31;
    __shared__ float ptsh[NT];
    __shared__ unsigned short psh[NT];
    // stage pt[0..smax] with float4 (smax+1 = s0+32 is a multiple of 32)
    for (int d4 = tid * 4; d4 <= smax; d4 += 1024)
        *(float4*)(ptsh + d4) = *(const float4*)(pt + d4);
    // stage full position list with uint4 (2048 shorts = 256 uint4)
    if (tid < 256)
        ((uint4*)psh)[tid] = ((const uint4*)(pos + b * NT))[tid];
    __syncthreads();

    float acc[2][32];
#pragma unroll
    for (int h = 0; h < 2; h++)
#pragma unroll
        for (int i = 0; i < 32; i++) acc[h][i] = 0.f;

    const int v0 = tid * 2;
    const int eA = off[b * (NV + 1) + v0];
    const int eB = off[b * (NV + 1) + v0 + 1];
    const int eC = off[b * (NV + 1) + v0 + 2];
#pragma unroll 1
    for (int h = 0; h < 2; h++) {
        const int e0 = h ? eB : eA, e1 = h ? eC : eB;
        for (int e = e0; e < e1; e++) {
            const int r = psh[e];
            if (r > smax) break;
            if (r <= s0) {
                const float* p = ptsh + (s0 - r);
#pragma unroll
                for (int i = 0; i < 32; i++) acc[h][i] += p[i];
            } else {
#pragma unroll
                for (int i = 0; i < 32; i++)
                    if (s0 + i >= r) acc[h][i] += ptsh[s0 + i - r];
            }
        }
    }
#pragma unroll
    for (int i = 0; i < 32; i++) {
        __nv_bfloat162 pk = __floats2bfloat162_rn(acc[0][i], acc[1][i]);
        *(__nv_bfloat162*)(L1 + ((size_t)(b * NT + s0 + i)) * NV + v0) = pk;
    }
}

// ---------------------------------------------------------------------------
// S-scatter grouped by query token q (atomic-free, single pass per (b,q))
// ---------------------------------------------------------------------------
__global__ void __launch_bounds__(512)
k_scatter_q(const unsigned short* __restrict__ pos, const int* __restrict__ off,
            const float* __restrict__ KT, __nv_bfloat16* __restrict__ S) {
    const int q = blockIdx.x, b = blockIdx.y;
    const int v = threadIdx.x;
    __shared__ float colsh[NT];
    __shared__ unsigned short psh[NT];
    __shared__ int tq0sh[2];

    if (v < 2) tq0sh[v] = off[b * (NV + 1) + q + v];
    __syncthreads();
    const int eq0 = tq0sh[0], eq1 = tq0sh[1];
    const int lenT = eq1 - eq0;
    if (lenT == 0) return;

    const unsigned short* pb = pos + b * NT;
    const int tlast = pb[eq1 - 1];

    {
        const float* src = KT + ((size_t)(b * NV + q)) * NT;
        for (int c4 = v; c4 * 4 <= tlast; c4 += 512) {
            uint32_t dst = smem_u32(&colsh[c4 * 4]);
            asm volatile("cp.async.cg.shared.global [%0], [%1], 16;" ::"r"(dst),
                         "l"(src + c4 * 4));
        }
        asm volatile("cp.async.commit_group;");
    }
    if (v < 256) ((uint4*)psh)[v] = ((const uint4*)pb)[v];
    asm volatile("cp.async.wait_group 0;");
    __syncthreads();

    int e = off[b * (NV + 1) + v];
    const int e1 = off[b * (NV + 1) + v + 1];
    float acc = 0.f;
    __nv_bfloat16* Sb = S + (size_t)b * NT * NV + v;
    for (int j = 0; j < lenT; j++) {
        const int t = psh[eq0 + j];
        while (e < e1 && psh[e] <= t) { acc += colsh[psh[e]]; e++; }
        Sb[(size_t)t * NV] = __float2bfloat16(acc);
    }
}

// ---------------------------------------------------------------------------
// bf16 GEMM, CTA 128x128, BK=32 (bf16), 8 warps of 64x32 each, 3-stage
// cp.async pipeline (one __syncthreads per k-iter), stride-20-u32 padded
// smem, ldmatrix fragment loads.
// B row-major [n][k]. C[m,n] = sum_k A[m,k]*B[n,k], fp32 out.
//   TRANS_OUT=true : C[m,n] -> KT[b][n][s] via shared-staged transpose
// ---------------------------------------------------------------------------
#define GSMEM 61440  // 3 stages * (A 2560 + B 2560) u32 = 15360 u32

template <bool TRANS_OUT>
__global__ void __launch_bounds__(256, 2)
gemm_bf16(const __nv_bfloat16* __restrict__ A,
          const __nv_bfloat16* __restrict__ Bsrc, float* __restrict__ C) {
    extern __shared__ __align__(16) uint32_t sm[];  // 15360 u32 = 60KB
    uint32_t* Asm = sm;          // [3][128][20] u32 (16 data + 4 pad per row)
    uint32_t* Bsm = sm + 7680;   // [3][128][20]

    const int tid = threadIdx.x;
    const int lane = tid & 31, warp = tid >> 5;
    const int wm = (warp & 1) * 64, wn = (warp >> 1) * 32;
    const int q = lane >> 2, t4 = lane & 3;
    const int m0 = blockIdx.y * BM, n0 = blockIdx.x * BN;

    // ldmatrix per-lane address offsets (u32 units, within one buffer)
    const int g = lane >> 3, lr = lane & 7;
    const int a_base = (wm + (g & 1) * 8 + lr) * 20 + (g >> 1) * 4;
    const int b_base = (wn + (g >> 1) * 8 + lr) * 20 + (g & 1) * 4;

    float c[4][4][4];
#pragma unroll
    for (int i = 0; i < 4; i++)
#pragma unroll
        for (int j = 0; j < 4; j++)
#pragma unroll
            for (int r = 0; r < 4; r++) c[i][j][r] = 0.f;

#define ISSUE_TILE(KT_, BUF_)                                                  \
    do {                                                                       \
        _Pragma("unroll") for (int i_ = 0; i_ < 2; i_++) {                     \
            int f = tid + i_ * 256;                                            \
            int m_ = f >> 2, k4 = f & 3;                                       \
            const __nv_bfloat16* src =                                         \
                A + (size_t)(m0 + m_) * NV + (KT_) + k4 * 8;                   \
            uint32_t dst =                                                     \
                smem_u32(&Asm[(BUF_)*2560 + m_ * 20 + k4 * 4]);                \
            asm volatile("cp.async.cg.shared.global [%0], [%1], 16;" ::"r"(    \
                             dst),                                             \
                         "l"(src));                                            \
        }                                                                      \
        _Pragma("unroll") for (int i_ = 0; i_ < 2; i_++) {                     \
            int f = tid + i_ * 256;                                            \
            int n_ = f >> 2, k4 = f & 3;                                       \
            const __nv_bfloat16* src =                                         \
                Bsrc + (size_t)(n0 + n_) * NV + (KT_) + k4 * 8;                \
            uint32_t dst =                                                     \
                smem_u32(&Bsm[(BUF_)*2560 + n_ * 20 + k4 * 4]);                \
            asm volatile("cp.async.cg.shared.global [%0], [%1], 16;" ::"r"(    \
                             dst),                                             \
                         "l"(src));                                            \
        }                                                                      \
        asm volatile("cp.async.commit_group;");                                \
    } while (0)

    // prologue: 2 tiles in flight
    ISSUE_TILE(0, 0);
    ISSUE_TILE(BK, 1);
    const int NKT = NV / BK;  // 16
#pragma unroll 1
    for (int it = 0; it < NKT; it++) {
        if (it + 1 < NKT) {
            asm volatile("cp.async.wait_group 1;");
        } else {
            asm volatile("cp.async.wait_group 0;");
        }
        __syncthreads();

        const int buf = it % 3;
        const uint32_t Abase = smem_u32(&Asm[buf * 2560]);
        const uint32_t Bbase = smem_u32(&Bsm[buf * 2560]);
#pragma unroll
        for (int ks = 0; ks < 2; ks++) {
            uint32_t a[4][4], bf_[4][2];
#pragma unroll
            for (int i = 0; i < 4; i++) {
                const uint32_t addr = Abase + (a_base + i * 320 + ks * 8) * 4;
                asm volatile(
                    "ldmatrix.sync.aligned.m8n8.x4.shared.b16 "
                    "{%0, %1, %2, %3}, [%4];"
                    : "=r"(a[i][0]), "=r"(a[i][1]), "=r"(a[i][2]), "=r"(a[i][3])
                    : "r"(addr));
            }
#pragma unroll
            for (int jj = 0; jj < 2; jj++) {
                const uint32_t addr = Bbase + (b_base + jj * 320 + ks * 8) * 4;
                asm volatile(
                    "ldmatrix.sync.aligned.m8n8.x4.shared.b16 "
                    "{%0, %1, %2, %3}, [%4];"
                    : "=r"(bf_[2 * jj][0]), "=r"(bf_[2 * jj][1]),
                      "=r"(bf_[2 * jj + 1][0]), "=r"(bf_[2 * jj + 1][1])
                    : "r"(addr));
            }
#pragma unroll
            for (int i = 0; i < 4; i++)
#pragma unroll
                for (int j = 0; j < 4; j++)
                    asm volatile(
                        "mma.sync.aligned.m16n8k16.row.col.f32.bf16.bf16.f32 "
                        "{%0,%1,%2,%3}, {%4,%5,%6,%7}, {%8,%9}, {%0,%1,%2,%3};"
                        : "+f"(c[i][j][0]), "+f"(c[i][j][1]),
                          "+f"(c[i][j][2]), "+f"(c[i][j][3])
                        : "r"(a[i][0]), "r"(a[i][1]), "r"(a[i][2]),
                          "r"(a[i][3]), "r"(bf_[j][0]), "r"(bf_[j][1]));
        }
        // issue tile it+2 into buf (it+2)%3 (compute of it-1 is fenced by the
        // barrier at this iteration's start)
        if (it + 2 < NKT) ISSUE_TILE((it + 2) * BK, (it + 2) % 3);
    }
#undef ISSUE_TILE
    __syncthreads();  // all reads of sm done before epilogue reuses it

    if (TRANS_OUT) {
        // C[m,n] -> KT[b][n][s], staged through shared for coalesced stores
        const int b = m0 >> 11;  // / NT
        const int s0 = m0 & (NT - 1);
        float* stg = (float*)sm;  // [64][136] floats = 34816B < 61440B
#pragma unroll
        for (int p = 0; p < 2; p++) {
            __syncthreads();
            if ((warp >> 2) == p) {
#pragma unroll
                for (int i = 0; i < 4; i++)
#pragma unroll
                    for (int j = 0; j < 4; j++)
#pragma unroll
                        for (int r = 0; r < 4; r++) {
                            int row = wm + i * 16 + q + (r >> 1) * 8;
                            int col = wn + j * 8 + 2 * t4 + (r & 1) - p * 64;
                            stg[col * 136 + row] = c[i][j][r];
                        }
            }
            __syncthreads();
            const int nn = tid >> 2, ch = tid & 3;
            float* dst = C + ((size_t)(b * NV + n0 + p * 64 + nn)) * NT + s0;
            const float* srow = stg + nn * 136;
#pragma unroll
            for (int w = 0; w < 8; w++) {
                int f = ch * 32 + w * 4;
                *(float4*)(dst + f) = *(const float4*)(srow + f);
            }
        }
    } else {
        float* Cb = C + (size_t)m0 * NV + n0;
#pragma unroll
        for (int i = 0; i < 4; i++)
#pragma unroll
            for (int j = 0; j < 4; j++) {
                const int row = wm + i * 16 + q;
                const int col = wn + j * 8 + 2 * t4;
                float2 v0 = make_float2(c[i][j][0], c[i][j][1]);
                float2 v1 = make_float2(c[i][j][2], c[i][j][3]);
                *(float2*)&Cb[(size_t)row * NV + col] = v0;
                *(float2*)&Cb[(size_t)(row + 8) * NV + col] = v1;
            }
    }
}

// ---------------------------------------------------------------------------
extern "C" void kernel_launch(void* const* d_in, const int* in_sizes, int n_in,
                              void* d_out, int out_size) {
    const int* idx = (const int*)d_in[0];     // (B,T) int32
    const float* pt = (const float*)d_in[1];  // (T,1) f32
    const float* Wq = (const float*)d_in[2];  // (V,V) f32
    const float* Wv = (const float*)d_in[3];  // (V,V) f32
    float* out = (float*)d_out;               // (B,T,V) f32

    __nv_bfloat16 *pA = nullptr, *pWqT = nullptr, *pWvR = nullptr;
    float* pKT = nullptr;
    unsigned short* pPos = nullptr;
    int *pOff = nullptr, *pCnt = nullptr, *pOff2 = nullptr;
    cudaGetSymbolAddress((void**)&pA, g_A);
    cudaGetSymbolAddress((void**)&pKT, g_KT);
    cudaGetSymbolAddress((void**)&pWqT, g_WqT);
    cudaGetSymbolAddress((void**)&pWvR, g_WvR);
    cudaGetSymbolAddress((void**)&pPos, g_pos);
    cudaGetSymbolAddress((void**)&pOff, g_off);
    cudaGetSymbolAddress((void**)&pCnt, g_cnt);
    cudaGetSymbolAddress((void**)&pOff2, g_off2);

    cudaFuncSetAttribute(gemm_bf16<true>,
                         cudaFuncAttributeMaxDynamicSharedMemorySize, GSMEM);
    cudaFuncSetAttribute(gemm_bf16<false>,
                         cudaFuncAttributeMaxDynamicSharedMemorySize, GSMEM);

    dim3 gridGemm(NV / BN, (NB * NT) / BM);  // (4, 256)

    // 0) weights to bf16 (WqT = Wq^T)
    k_wqt<<<dim3(16, 16), dim3(32, 8)>>>(Wq, pWqT);
    k_wv<<<(NV * NV) / 1024, 256>>>(Wv, pWvR);
    // 1) CSR of token positions per batch (parallel: hist -> scan -> fill)
    k_hist<<<dim3(NCH, NB), 512>>>(idx, pCnt);
    k_scan<<<NB, 512>>>(pCnt, pOff, pOff2);
    k_fill<<<dim3(NCH, NB), 512>>>(idx, pOff2, pPos);
    // 2) L1 scatter (atomic-free via CSR), bf16 out
    k_build_l1<<<dim3(NT / 32, NB), 256>>>(pPos, pOff, pt, pA);
    // 3) K = L1 @ Wq -> KT[b][n][s] fp32
    gemm_bf16<true><<<gridGemm, 256, GSMEM>>>(pA, pWqT, pKT);
    // 4) S scatter grouped by q (atomic-free, single pass), bf16 out
    k_scatter_q<<<dim3(NV, NB), 512>>>(pPos, pOff, pKT, pA);
    // 5) logits = S @ Wv^T, fp32 out
    gemm_bf16<false><<<gridGemm, 256, GSMEM>>>(pA, pWvR, out);
}

// round 12
// speedup vs baseline: 1.1244x; 1.1244x over previous
#include <cuda_runtime.h>
#include <cuda_bf16.h>
#include <cstdint>

#define NB 16
#define NT 2048
#define NV 512
#define BM 128
#define BN 128
#define BK 32    // bf16 elements per k-tile
#define NCH 16
#define CHW (NT / NCH)  // 128

// Scratch (allocation-free rule: __device__ globals).
__device__ __nv_bfloat16 g_A[(size_t)NB * NT * NV];   // L1, then reused as S
__device__ float g_KT[(size_t)NB * NV * NT];          // K transposed per batch
__device__ __nv_bfloat16 g_WqT[NV * NV];              // Wq^T in bf16, [n][k]
__device__ __nv_bfloat16 g_WvR[NV * NV];              // Wv in bf16, [n][k]
__device__ unsigned short g_pos[NB * NT];             // CSR positions (sorted)
__device__ int g_off[NB * (NV + 1)];                  // CSR offsets
__device__ int g_cnt[NB * NCH * NV];                  // per-chunk counts
__device__ int g_off2[NB * NCH * NV];                 // per-chunk start offsets

__device__ __forceinline__ uint32_t smem_u32(const void* p) {
    return (uint32_t)__cvta_generic_to_shared(p);
}

// ---------------------------------------------------------------------------
// Wq transpose (512x512) -> bf16, [n][k] layout
// ---------------------------------------------------------------------------
__global__ void k_wqt(const float* __restrict__ W, __nv_bfloat16* __restrict__ WT) {
    __shared__ float t[32][33];
    int x = blockIdx.x * 32 + threadIdx.x;
    int y = blockIdx.y * 32 + threadIdx.y;
#pragma unroll
    for (int j = 0; j < 32; j += 8)
        t[threadIdx.y + j][threadIdx.x] = W[(size_t)(y + j) * NV + x];
    __syncthreads();
    x = blockIdx.y * 32 + threadIdx.x;
    y = blockIdx.x * 32 + threadIdx.y;
#pragma unroll
    for (int j = 0; j < 32; j += 8)
        WT[(size_t)(y + j) * NV + x] = __float2bfloat16(t[threadIdx.x][threadIdx.y + j]);
}

// ---------------------------------------------------------------------------
// Wv -> bf16 copy
// ---------------------------------------------------------------------------
__global__ void k_wv(const float* __restrict__ src, __nv_bfloat16* __restrict__ dst) {
    int i4 = (blockIdx.x * 256 + threadIdx.x) * 4;
    float4 v = *(const float4*)(src + i4);
    __nv_bfloat162* d2 = (__nv_bfloat162*)(dst + i4);
    d2[0] = __floats2bfloat162_rn(v.x, v.y);
    d2[1] = __floats2bfloat162_rn(v.z, v.w);
}

// ---------------------------------------------------------------------------
// Parallel CSR build: hist (per 128-token chunk) -> scan -> fill
// ---------------------------------------------------------------------------
__global__ void k_hist(const int* __restrict__ idx, int* __restrict__ cnt) {
    const int c = blockIdx.x, b = blockIdx.y, v = threadIdx.x;
    __shared__ int sidx[CHW];
    if (v < CHW) sidx[v] = idx[b * NT + c * CHW + v];
    __syncthreads();
    int n = 0;
#pragma unroll 8
    for (int r = 0; r < CHW; r++) n += (sidx[r] == v);
    cnt[(b * NCH + c) * NV + v] = n;
}

__global__ void k_scan(const int* __restrict__ cnt, int* __restrict__ off,
                       int* __restrict__ off2) {
    const int b = blockIdx.x, v = threadIdx.x;
    __shared__ int wsum[16];
    int c[NCH];
    int tot = 0;
#pragma unroll
    for (int j = 0; j < NCH; j++) {
        c[j] = cnt[(b * NCH + j) * NV + v];
        tot += c[j];
    }
    const int lane = v & 31, w = v >> 5;
    int incl = tot;
#pragma unroll
    for (int d = 1; d < 32; d <<= 1) {
        int x = __shfl_up_sync(0xffffffffu, incl, d);
        if (lane >= d) incl += x;
    }
    if (lane == 31) wsum[w] = incl;
    __syncthreads();
    if (w == 0) {
        int s = (lane < 16) ? wsum[lane] : 0;
#pragma unroll
        for (int d = 1; d < 16; d <<= 1) {
            int x = __shfl_up_sync(0xffffffffu, s, d);
            if (lane >= d) s += x;
        }
        if (lane < 16) wsum[lane] = s;
    }
    __syncthreads();
    int o = incl - tot + (w ? wsum[w - 1] : 0);  // exclusive prefix
    off[b * (NV + 1) + v] = o;
    if (v == NV - 1) off[b * (NV + 1) + NV] = NT;
#pragma unroll
    for (int j = 0; j < NCH; j++) {
        off2[(b * NCH + j) * NV + v] = o;
        o += c[j];
    }
}

__global__ void k_fill(const int* __restrict__ idx, const int* __restrict__ off2,
                       unsigned short* __restrict__ pos) {
    const int c = blockIdx.x, b = blockIdx.y, v = threadIdx.x;
    __shared__ int sidx[CHW];
    if (v < CHW) sidx[v] = idx[b * NT + c * CHW + v];
    __syncthreads();
    int o = off2[(b * NCH + c) * NV + v];
    for (int r = 0; r < CHW; r++)
        if (sidx[r] == v) pos[b * NT + (o++)] = (unsigned short)(c * CHW + r);
}

// ---------------------------------------------------------------------------
// L1[b,s,v] = sum_{r<=s, idx[b,r]==v} pt[s-r], atomic-free via CSR.
// (R10 version: 512 threads, 1 vocab per thread — measured good.)
// ---------------------------------------------------------------------------
__global__ void __launch_bounds__(512)
k_build_l1(const unsigned short* __restrict__ pos, const int* __restrict__ off,
           const float* __restrict__ pt, __nv_bfloat16* __restrict__ L1) {
    const int s0 = blockIdx.x * 32, b = blockIdx.y;
    const int v = threadIdx.x;
    const int smax = s0 + 31;
    __shared__ float ptsh[NT];
    __shared__ unsigned short psh[NT];
    for (int d = v; d <= smax; d += 512) ptsh[d] = pt[d];
    for (int d = v; d < NT; d += 512) psh[d] = pos[b * NT + d];
    __syncthreads();
    float acc[32];
#pragma unroll
    for (int i = 0; i < 32; i++) acc[i] = 0.f;
    const int e0 = off[b * (NV + 1) + v], e1 = off[b * (NV + 1) + v + 1];
    for (int e = e0; e < e1; e++) {
        const int r = psh[e];
        if (r > smax) break;
        if (r <= s0) {
            const float* p = ptsh + (s0 - r);
#pragma unroll
            for (int i = 0; i < 32; i++) acc[i] += p[i];
        } else {
#pragma unroll
            for (int i = 0; i < 32; i++)
                if (s0 + i >= r) acc[i] += ptsh[s0 + i - r];
        }
    }
#pragma unroll
    for (int i = 0; i < 32; i++)
        L1[((size_t)(b * NT + s0 + i)) * NV + v] = __float2bfloat16(acc[i]);
}

// ---------------------------------------------------------------------------
// S-scatter grouped by query token q (atomic-free, single pass per (b,q))
// (R10 version — measured good.)
// ---------------------------------------------------------------------------
__global__ void __launch_bounds__(512)
k_scatter_q(const unsigned short* __restrict__ pos, const int* __restrict__ off,
            const float* __restrict__ KT, __nv_bfloat16* __restrict__ S) {
    const int q = blockIdx.x, b = blockIdx.y;
    const int v = threadIdx.x;
    __shared__ float colsh[NT];
    __shared__ unsigned short psh[NT];
    __shared__ int tq0sh[2];

    if (v < 2) tq0sh[v] = off[b * (NV + 1) + q + v];
    __syncthreads();
    const int eq0 = tq0sh[0], eq1 = tq0sh[1];
    const int lenT = eq1 - eq0;
    if (lenT == 0) return;

    const unsigned short* pb = pos + b * NT;
    const int tlast = pb[eq1 - 1];

    {
        const float* src = KT + ((size_t)(b * NV + q)) * NT;
        for (int c4 = v; c4 * 4 <= tlast; c4 += 512) {
            uint32_t dst = smem_u32(&colsh[c4 * 4]);
            asm volatile("cp.async.cg.shared.global [%0], [%1], 16;" ::"r"(dst),
                         "l"(src + c4 * 4));
        }
        asm volatile("cp.async.commit_group;");
    }
    for (int d = v; d < NT; d += 512) psh[d] = pb[d];
    asm volatile("cp.async.wait_group 0;");
    __syncthreads();

    int e = off[b * (NV + 1) + v];
    const int e1 = off[b * (NV + 1) + v + 1];
    float acc = 0.f;
    __nv_bfloat16* Sb = S + (size_t)b * NT * NV + v;
    for (int j = 0; j < lenT; j++) {
        const int t = psh[eq0 + j];
        while (e < e1 && psh[e] <= t) { acc += colsh[psh[e]]; e++; }
        Sb[(size_t)t * NV] = __float2bfloat16(acc);
    }
}

// ---------------------------------------------------------------------------
// bf16 GEMM, CTA 128x128, BK=32 (bf16), 8 warps of 64x32 each, 3-stage
// cp.async pipeline (issue it+2 right after the barrier, before compute),
// stride-20-u32 padded smem, ldmatrix fragment loads.
// B row-major [n][k]. C[m,n] = sum_k A[m,k]*B[n,k], fp32 out.
//   TRANS_OUT=true : C[m,n] -> KT[b][n][s] via shared-staged transpose
// ---------------------------------------------------------------------------
#define GSMEM 61440  // 3 stages * (A 2560 + B 2560) u32 = 15360 u32

template <bool TRANS_OUT>
__global__ void __launch_bounds__(256, 2)
gemm_bf16(const __nv_bfloat16* __restrict__ A,
          const __nv_bfloat16* __restrict__ Bsrc, float* __restrict__ C) {
    extern __shared__ __align__(16) uint32_t sm[];  // 15360 u32 = 60KB
    uint32_t* Asm = sm;          // [3][128][20] u32 (16 data + 4 pad per row)
    uint32_t* Bsm = sm + 7680;   // [3][128][20]

    const int tid = threadIdx.x;
    const int lane = tid & 31, warp = tid >> 5;
    const int wm = (warp & 1) * 64, wn = (warp >> 1) * 32;
    const int q = lane >> 2, t4 = lane & 3;
    const int m0 = blockIdx.y * BM, n0 = blockIdx.x * BN;

    // ldmatrix per-lane address offsets (u32 units, within one buffer)
    const int g = lane >> 3, lr = lane & 7;
    const int a_base = (wm + (g & 1) * 8 + lr) * 20 + (g >> 1) * 4;
    const int b_base = (wn + (g >> 1) * 8 + lr) * 20 + (g & 1) * 4;

    float c[4][4][4];
#pragma unroll
    for (int i = 0; i < 4; i++)
#pragma unroll
        for (int j = 0; j < 4; j++)
#pragma unroll
            for (int r = 0; r < 4; r++) c[i][j][r] = 0.f;

#define ISSUE_TILE(KT_, BUF_)                                                  \
    do {                                                                       \
        _Pragma("unroll") for (int i_ = 0; i_ < 2; i_++) {                     \
            int f = tid + i_ * 256;                                            \
            int m_ = f >> 2, k4 = f & 3;                                       \
            const __nv_bfloat16* src =                                         \
                A + (size_t)(m0 + m_) * NV + (KT_) + k4 * 8;                   \
            uint32_t dst =                                                     \
                smem_u32(&Asm[(BUF_)*2560 + m_ * 20 + k4 * 4]);                \
            asm volatile("cp.async.cg.shared.global [%0], [%1], 16;" ::"r"(    \
                             dst),                                             \
                         "l"(src));                                            \
        }                                                                      \
        _Pragma("unroll") for (int i_ = 0; i_ < 2; i_++) {                     \
            int f = tid + i_ * 256;                                            \
            int n_ = f >> 2, k4 = f & 3;                                       \
            const __nv_bfloat16* src =                                         \
                Bsrc + (size_t)(n0 + n_) * NV + (KT_) + k4 * 8;                \
            uint32_t dst =                                                     \
                smem_u32(&Bsm[(BUF_)*2560 + n_ * 20 + k4 * 4]);                \
            asm volatile("cp.async.cg.shared.global [%0], [%1], 16;" ::"r"(    \
                             dst),                                             \
                         "l"(src));                                            \
        }                                                                      \
        asm volatile("cp.async.commit_group;");                                \
    } while (0)

    // prologue: 2 tiles in flight
    ISSUE_TILE(0, 0);
    ISSUE_TILE(BK, 1);
    const int NKT = NV / BK;  // 16
#pragma unroll 1
    for (int it = 0; it < NKT; it++) {
        if (it + 1 < NKT) {
            asm volatile("cp.async.wait_group 1;");
        } else {
            asm volatile("cp.async.wait_group 0;");
        }
        __syncthreads();
        // issue tile it+2 into buf (it+2)%3 == (it-1)%3; all reads of that
        // buffer finished in iteration it-1, fenced by the barrier above.
        if (it + 2 < NKT) ISSUE_TILE((it + 2) * BK, (it + 2) % 3);

        const int buf = it % 3;
        const uint32_t Abase = smem_u32(&Asm[buf * 2560]);
        const uint32_t Bbase = smem_u32(&Bsm[buf * 2560]);
#pragma unroll
        for (int ks = 0; ks < 2; ks++) {
            uint32_t a[4][4], bf_[4][2];
#pragma unroll
            for (int i = 0; i < 4; i++) {
                const uint32_t addr = Abase + (a_base + i * 320 + ks * 8) * 4;
                asm volatile(
                    "ldmatrix.sync.aligned.m8n8.x4.shared.b16 "
                    "{%0, %1, %2, %3}, [%4];"
                    : "=r"(a[i][0]), "=r"(a[i][1]), "=r"(a[i][2]), "=r"(a[i][3])
                    : "r"(addr));
            }
#pragma unroll
            for (int jj = 0; jj < 2; jj++) {
                const uint32_t addr = Bbase + (b_base + jj * 320 + ks * 8) * 4;
                asm volatile(
                    "ldmatrix.sync.aligned.m8n8.x4.shared.b16 "
                    "{%0, %1, %2, %3}, [%4];"
                    : "=r"(bf_[2 * jj][0]), "=r"(bf_[2 * jj][1]),
                      "=r"(bf_[2 * jj + 1][0]), "=r"(bf_[2 * jj + 1][1])
                    : "r"(addr));
            }
#pragma unroll
            for (int i = 0; i < 4; i++)
#pragma unroll
                for (int j = 0; j < 4; j++)
                    asm volatile(
                        "mma.sync.aligned.m16n8k16.row.col.f32.bf16.bf16.f32 "
                        "{%0,%1,%2,%3}, {%4,%5,%6,%7}, {%8,%9}, {%0,%1,%2,%3};"
                        : "+f"(c[i][j][0]), "+f"(c[i][j][1]),
                          "+f"(c[i][j][2]), "+f"(c[i][j][3])
                        : "r"(a[i][0]), "r"(a[i][1]), "r"(a[i][2]),
                          "r"(a[i][3]), "r"(bf_[j][0]), "r"(bf_[j][1]));
        }
    }
#undef ISSUE_TILE
    __syncthreads();  // all reads of sm done before epilogue reuses it

    if (TRANS_OUT) {
        // C[m,n] -> KT[b][n][s], staged through shared for coalesced stores
        const int b = m0 >> 11;  // / NT
        const int s0 = m0 & (NT - 1);
        float* stg = (float*)sm;  // [64][136] floats = 34816B < 61440B
#pragma unroll
        for (int p = 0; p < 2; p++) {
            __syncthreads();
            if ((warp >> 2) == p) {
#pragma unroll
                for (int i = 0; i < 4; i++)
#pragma unroll
                    for (int j = 0; j < 4; j++)
#pragma unroll
                        for (int r = 0; r < 4; r++) {
                            int row = wm + i * 16 + q + (r >> 1) * 8;
                            int col = wn + j * 8 + 2 * t4 + (r & 1) - p * 64;
                            stg[col * 136 + row] = c[i][j][r];
                        }
            }
            __syncthreads();
            const int nn = tid >> 2, ch = tid & 3;
            float* dst = C + ((size_t)(b * NV + n0 + p * 64 + nn)) * NT + s0;
            const float* srow = stg + nn * 136;
#pragma unroll
            for (int w = 0; w < 8; w++) {
                int f = ch * 32 + w * 4;
                *(float4*)(dst + f) = *(const float4*)(srow + f);
            }
        }
    } else {
        float* Cb = C + (size_t)m0 * NV + n0;
#pragma unroll
        for (int i = 0; i < 4; i++)
#pragma unroll
            for (int j = 0; j < 4; j++) {
                const int row = wm + i * 16 + q;
                const int col = wn + j * 8 + 2 * t4;
                float2 v0 = make_float2(c[i][j][0], c[i][j][1]);
                float2 v1 = make_float2(c[i][j][2], c[i][j][3]);
                *(float2*)&Cb[(size_t)row * NV + col] = v0;
                *(float2*)&Cb[(size_t)(row + 8) * NV + col] = v1;
            }
    }
}

// ---------------------------------------------------------------------------
extern "C" void kernel_launch(void* const* d_in, const int* in_sizes, int n_in,
                              void* d_out, int out_size) {
    const int* idx = (const int*)d_in[0];     // (B,T) int32
    const float* pt = (const float*)d_in[1];  // (T,1) f32
    const float* Wq = (const float*)d_in[2];  // (V,V) f32
    const float* Wv = (const float*)d_in[3];  // (V,V) f32
    float* out = (float*)d_out;               // (B,T,V) f32

    __nv_bfloat16 *pA = nullptr, *pWqT = nullptr, *pWvR = nullptr;
    float* pKT = nullptr;
    unsigned short* pPos = nullptr;
    int *pOff = nullptr, *pCnt = nullptr, *pOff2 = nullptr;
    cudaGetSymbolAddress((void**)&pA, g_A);
    cudaGetSymbolAddress((void**)&pKT, g_KT);
    cudaGetSymbolAddress((void**)&pWqT, g_WqT);
    cudaGetSymbolAddress((void**)&pWvR, g_WvR);
    cudaGetSymbolAddress((void**)&pPos, g_pos);
    cudaGetSymbolAddress((void**)&pOff, g_off);
    cudaGetSymbolAddress((void**)&pCnt, g_cnt);
    cudaGetSymbolAddress((void**)&pOff2, g_off2);

    cudaFuncSetAttribute(gemm_bf16<true>,
                         cudaFuncAttributeMaxDynamicSharedMemorySize, GSMEM);
    cudaFuncSetAttribute(gemm_bf16<false>,
                         cudaFuncAttributeMaxDynamicSharedMemorySize, GSMEM);

    dim3 gridGemm(NV / BN, (NB * NT) / BM);  // (4, 256)

    // 0) weights to bf16 (WqT = Wq^T)
    k_wqt<<<dim3(16, 16), dim3(32, 8)>>>(Wq, pWqT);
    k_wv<<<(NV * NV) / 1024, 256>>>(Wv, pWvR);
    // 1) CSR of token positions per batch (parallel: hist -> scan -> fill)
    k_hist<<<dim3(NCH, NB), 512>>>(idx, pCnt);
    k_scan<<<NB, 512>>>(pCnt, pOff, pOff2);
    k_fill<<<dim3(NCH, NB), 512>>>(idx, pOff2, pPos);
    // 2) L1 scatter (atomic-free via CSR), bf16 out
    k_build_l1<<<dim3(NT / 32, NB), 512>>>(pPos, pOff, pt, pA);
    // 3) K = L1 @ Wq -> KT[b][n][s] fp32
    gemm_bf16<true><<<gridGemm, 256, GSMEM>>>(pA, pWqT, pKT);
    // 4) S scatter grouped by q (atomic-free, single pass), bf16 out
    k_scatter_q<<<dim3(NV, NB), 512>>>(pPos, pOff, pKT, pA);
    // 5) logits = S @ Wv^T, fp32 out
    gemm_bf16<false><<<gridGemm, 256, GSMEM>>>(pA, pWvR, out);
}

// round 14
// speedup vs baseline: 1.2217x; 1.0865x over previous
#include <cuda_runtime.h>
#include <cuda_bf16.h>
#include <cstdint>

#define NB 16
#define NT 2048
#define NV 512
#define BM 128
#define BN 128
#define BK 32    // bf16 elements per k-tile
#define NCH 16
#define CHW (NT / NCH)  // 128

// Scratch (allocation-free rule: __device__ globals).
__device__ __nv_bfloat16 g_A[(size_t)NB * NT * NV];   // L1, then reused as S
__device__ __nv_bfloat16 g_KT[(size_t)NB * NV * NT];  // K^T per batch (bf16)
__device__ __nv_bfloat16 g_WqT[NV * NV];              // Wq^T in bf16, [n][k]
__device__ __nv_bfloat16 g_WvR[NV * NV];              // Wv in bf16, [n][k]
__device__ unsigned short g_pos[NB * NT];             // CSR positions (sorted)
__device__ int g_off[NB * (NV + 1)];                  // CSR offsets
__device__ int g_cnt[NB * NCH * NV];                  // per-chunk counts
__device__ int g_off2[NB * NCH * NV];                 // per-chunk start offsets

__device__ __forceinline__ uint32_t smem_u32(const void* p) {
    return (uint32_t)__cvta_generic_to_shared(p);
}

// ---------------------------------------------------------------------------
// Wq transpose (512x512) -> bf16, [n][k] layout
// ---------------------------------------------------------------------------
__global__ void k_wqt(const float* __restrict__ W, __nv_bfloat16* __restrict__ WT) {
    __shared__ float t[32][33];
    int x = blockIdx.x * 32 + threadIdx.x;
    int y = blockIdx.y * 32 + threadIdx.y;
#pragma unroll
    for (int j = 0; j < 32; j += 8)
        t[threadIdx.y + j][threadIdx.x] = W[(size_t)(y + j) * NV + x];
    __syncthreads();
    x = blockIdx.y * 32 + threadIdx.x;
    y = blockIdx.x * 32 + threadIdx.y;
#pragma unroll
    for (int j = 0; j < 32; j += 8)
        WT[(size_t)(y + j) * NV + x] = __float2bfloat16(t[threadIdx.x][threadIdx.y + j]);
}

// ---------------------------------------------------------------------------
// Wv -> bf16 copy
// ---------------------------------------------------------------------------
__global__ void k_wv(const float* __restrict__ src, __nv_bfloat16* __restrict__ dst) {
    int i4 = (blockIdx.x * 256 + threadIdx.x) * 4;
    float4 v = *(const float4*)(src + i4);
    __nv_bfloat162* d2 = (__nv_bfloat162*)(dst + i4);
    d2[0] = __floats2bfloat162_rn(v.x, v.y);
    d2[1] = __floats2bfloat162_rn(v.z, v.w);
}

// ---------------------------------------------------------------------------
// Parallel CSR build: hist (per 128-token chunk) -> scan -> fill
// ---------------------------------------------------------------------------
__global__ void k_hist(const int* __restrict__ idx, int* __restrict__ cnt) {
    const int c = blockIdx.x, b = blockIdx.y, v = threadIdx.x;
    __shared__ int sidx[CHW];
    if (v < CHW) sidx[v] = idx[b * NT + c * CHW + v];
    __syncthreads();
    int n = 0;
#pragma unroll 8
    for (int r = 0; r < CHW; r++) n += (sidx[r] == v);
    cnt[(b * NCH + c) * NV + v] = n;
}

__global__ void k_scan(const int* __restrict__ cnt, int* __restrict__ off,
                       int* __restrict__ off2) {
    const int b = blockIdx.x, v = threadIdx.x;
    __shared__ int wsum[16];
    int c[NCH];
    int tot = 0;
#pragma unroll
    for (int j = 0; j < NCH; j++) {
        c[j] = cnt[(b * NCH + j) * NV + v];
        tot += c[j];
    }
    const int lane = v & 31, w = v >> 5;
    int incl = tot;
#pragma unroll
    for (int d = 1; d < 32; d <<= 1) {
        int x = __shfl_up_sync(0xffffffffu, incl, d);
        if (lane >= d) incl += x;
    }
    if (lane == 31) wsum[w] = incl;
    __syncthreads();
    if (w == 0) {
        int s = (lane < 16) ? wsum[lane] : 0;
#pragma unroll
        for (int d = 1; d < 16; d <<= 1) {
            int x = __shfl_up_sync(0xffffffffu, s, d);
            if (lane >= d) s += x;
        }
        if (lane < 16) wsum[lane] = s;
    }
    __syncthreads();
    int o = incl - tot + (w ? wsum[w - 1] : 0);  // exclusive prefix
    off[b * (NV + 1) + v] = o;
    if (v == NV - 1) off[b * (NV + 1) + NV] = NT;
#pragma unroll
    for (int j = 0; j < NCH; j++) {
        off2[(b * NCH + j) * NV + v] = o;
        o += c[j];
    }
}

__global__ void k_fill(const int* __restrict__ idx, const int* __restrict__ off2,
                       unsigned short* __restrict__ pos) {
    const int c = blockIdx.x, b = blockIdx.y, v = threadIdx.x;
    __shared__ int sidx[CHW];
    if (v < CHW) sidx[v] = idx[b * NT + c * CHW + v];
    __syncthreads();
    int o = off2[(b * NCH + c) * NV + v];
    for (int r = 0; r < CHW; r++)
        if (sidx[r] == v) pos[b * NT + (o++)] = (unsigned short)(c * CHW + r);
}

// ---------------------------------------------------------------------------
// L1[b,s,v] = sum_{r<=s, idx[b,r]==v} pt[s-r], atomic-free via CSR.
// 512 threads, 1 vocab per thread (R10 structure). pt staged as 4 shifted
// copies (ptc[a][f] = pt[f+a]) so the 32-add burst uses 8x LDS.128.
// ---------------------------------------------------------------------------
__global__ void __launch_bounds__(512)
k_build_l1(const unsigned short* __restrict__ pos, const int* __restrict__ off,
           const float* __restrict__ pt, __nv_bfloat16* __restrict__ L1) {
    const int s0 = blockIdx.x * 32, b = blockIdx.y;
    const int v = threadIdx.x;
    const int smax = s0 + 31;
    __shared__ __align__(16) float ptc[4][NT];
    __shared__ unsigned short psh[NT];
    for (int f = v; f <= smax; f += 512) {
        ptc[0][f] = pt[f];
        ptc[1][f] = pt[f + 1 < NT ? f + 1 : NT - 1];
        ptc[2][f] = pt[f + 2 < NT ? f + 2 : NT - 1];
        ptc[3][f] = pt[f + 3 < NT ? f + 3 : NT - 1];
    }
    for (int d = v; d < NT; d += 512) psh[d] = pos[b * NT + d];
    __syncthreads();
    float acc[32];
#pragma unroll
    for (int i = 0; i < 32; i++) acc[i] = 0.f;
    const int e0 = off[b * (NV + 1) + v], e1 = off[b * (NV + 1) + v + 1];
    for (int e = e0; e < e1; e++) {
        const int r = psh[e];
        if (r > smax) break;
        const int d = s0 - r;
        if (d >= 0) {
            const int a = d & 3;
            const float4* p4 = (const float4*)&ptc[a][d - a];
#pragma unroll
            for (int k = 0; k < 8; k++) {
                float4 q4 = p4[k];
                acc[4 * k + 0] += q4.x;
                acc[4 * k + 1] += q4.y;
                acc[4 * k + 2] += q4.z;
                acc[4 * k + 3] += q4.w;
            }
        } else {
#pragma unroll
            for (int i = 0; i < 32; i++)
                if (s0 + i >= r) acc[i] += ptc[0][s0 + i - r];
        }
    }
#pragma unroll
    for (int i = 0; i < 32; i++)
        L1[((size_t)(b * NT + s0 + i)) * NV + v] = __float2bfloat16(acc[i]);
}

// ---------------------------------------------------------------------------
// S-scatter grouped by query token q (atomic-free, single pass per (b,q)).
// KT is bf16 now; accumulation stays fp32.
// ---------------------------------------------------------------------------
__global__ void __launch_bounds__(512)
k_scatter_q(const unsigned short* __restrict__ pos, const int* __restrict__ off,
            const __nv_bfloat16* __restrict__ KT, __nv_bfloat16* __restrict__ S) {
    const int q = blockIdx.x, b = blockIdx.y;
    const int v = threadIdx.x;
    __shared__ __align__(16) __nv_bfloat16 colsh[NT];
    __shared__ unsigned short psh[NT];
    __shared__ int tq0sh[2];

    if (v < 2) tq0sh[v] = off[b * (NV + 1) + q + v];
    __syncthreads();
    const int eq0 = tq0sh[0], eq1 = tq0sh[1];
    const int lenT = eq1 - eq0;
    if (lenT == 0) return;

    const unsigned short* pb = pos + b * NT;
    const int tlast = pb[eq1 - 1];

    {
        const __nv_bfloat16* src = KT + ((size_t)(b * NV + q)) * NT;
        for (int c8 = v; c8 * 8 <= tlast; c8 += 512) {
            uint32_t dst = smem_u32(colsh + c8 * 8);
            asm volatile("cp.async.cg.shared.global [%0], [%1], 16;" ::"r"(dst),
                         "l"(src + c8 * 8));
        }
        asm volatile("cp.async.commit_group;");
    }
    for (int d = v; d < NT; d += 512) psh[d] = pb[d];
    asm volatile("cp.async.wait_group 0;");
    __syncthreads();

    int e = off[b * (NV + 1) + v];
    const int e1 = off[b * (NV + 1) + v + 1];
    float acc = 0.f;
    __nv_bfloat16* Sb = S + (size_t)b * NT * NV + v;
    for (int j = 0; j < lenT; j++) {
        const int t = psh[eq0 + j];
        while (e < e1 && psh[e] <= t) {
            acc += __bfloat162float(colsh[psh[e]]);
            e++;
        }
        Sb[(size_t)t * NV] = __float2bfloat16(acc);
    }
}

// ---------------------------------------------------------------------------
// bf16 GEMM, CTA 128x128, BK=32 (bf16), 8 warps of 64x32 each, 3-stage
// cp.async pipeline (issue it+2 right after the barrier, before compute),
// stride-20-u32 padded smem, ldmatrix fragment loads.
// B row-major [n][k]. C[m,n] = sum_k A[m,k]*B[n,k].
//   TRANS_OUT=true : C[m,n] -> KT[b][n][s] (bf16) via shared-staged transpose
//   TRANS_OUT=false: row-major fp32 out
// ---------------------------------------------------------------------------
#define GSMEM 61440  // 3 stages * (A 2560 + B 2560) u32 = 15360 u32

template <bool TRANS_OUT>
__global__ void __launch_bounds__(256, 2)
gemm_bf16(const __nv_bfloat16* __restrict__ A,
          const __nv_bfloat16* __restrict__ Bsrc, void* __restrict__ Cv) {
    extern __shared__ __align__(16) uint32_t sm[];  // 15360 u32 = 60KB
    uint32_t* Asm = sm;          // [3][128][20] u32 (16 data + 4 pad per row)
    uint32_t* Bsm = sm + 7680;   // [3][128][20]

    const int tid = threadIdx.x;
    const int lane = tid & 31, warp = tid >> 5;
    const int wm = (warp & 1) * 64, wn = (warp >> 1) * 32;
    const int q = lane >> 2, t4 = lane & 3;
    const int m0 = blockIdx.y * BM, n0 = blockIdx.x * BN;

    // ldmatrix per-lane address offsets (u32 units, within one buffer)
    const int g = lane >> 3, lr = lane & 7;
    const int a_base = (wm + (g & 1) * 8 + lr) * 20 + (g >> 1) * 4;
    const int b_base = (wn + (g >> 1) * 8 + lr) * 20 + (g & 1) * 4;

    float c[4][4][4];
#pragma unroll
    for (int i = 0; i < 4; i++)
#pragma unroll
        for (int j = 0; j < 4; j++)
#pragma unroll
            for (int r = 0; r < 4; r++) c[i][j][r] = 0.f;

#define ISSUE_TILE(KT_, BUF_)                                                  \
    do {                                                                       \
        _Pragma("unroll") for (int i_ = 0; i_ < 2; i_++) {                     \
            int f = tid + i_ * 256;                                            \
            int m_ = f >> 2, k4 = f & 3;                                       \
            const __nv_bfloat16* src =                                         \
                A + (size_t)(m0 + m_) * NV + (KT_) + k4 * 8;                   \
            uint32_t dst =                                                     \
                smem_u32(&Asm[(BUF_)*2560 + m_ * 20 + k4 * 4]);                \
            asm volatile("cp.async.cg.shared.global [%0], [%1], 16;" ::"r"(    \
                             dst),                                             \
                         "l"(src));                                            \
        }                                                                      \
        _Pragma("unroll") for (int i_ = 0; i_ < 2; i_++) {                     \
            int f = tid + i_ * 256;                                            \
            int n_ = f >> 2, k4 = f & 3;                                       \
            const __nv_bfloat16* src =                                         \
                Bsrc + (size_t)(n0 + n_) * NV + (KT_) + k4 * 8;                \
            uint32_t dst =                                                     \
                smem_u32(&Bsm[(BUF_)*2560 + n_ * 20 + k4 * 4]);                \
            asm volatile("cp.async.cg.shared.global [%0], [%1], 16;" ::"r"(    \
                             dst),                                             \
                         "l"(src));                                            \
        }                                                                      \
        asm volatile("cp.async.commit_group;");                                \
    } while (0)

    // prologue: 2 tiles in flight
    ISSUE_TILE(0, 0);
    ISSUE_TILE(BK, 1);
    const int NKT = NV / BK;  // 16
#pragma unroll 1
    for (int it = 0; it < NKT; it++) {
        if (it + 1 < NKT) {
            asm volatile("cp.async.wait_group 1;");
        } else {
            asm volatile("cp.async.wait_group 0;");
        }
        __syncthreads();
        // issue tile it+2 into buf (it+2)%3 == (it-1)%3; all reads of that
        // buffer finished in iteration it-1, fenced by the barrier above.
        if (it + 2 < NKT) ISSUE_TILE((it + 2) * BK, (it + 2) % 3);

        const int buf = it % 3;
        const uint32_t Abase = smem_u32(&Asm[buf * 2560]);
        const uint32_t Bbase = smem_u32(&Bsm[buf * 2560]);
#pragma unroll
        for (int ks = 0; ks < 2; ks++) {
            uint32_t a[4][4], bf_[4][2];
#pragma unroll
            for (int i = 0; i < 4; i++) {
                const uint32_t addr = Abase + (a_base + i * 320 + ks * 8) * 4;
                asm volatile(
                    "ldmatrix.sync.aligned.m8n8.x4.shared.b16 "
                    "{%0, %1, %2, %3}, [%4];"
                    : "=r"(a[i][0]), "=r"(a[i][1]), "=r"(a[i][2]), "=r"(a[i][3])
                    : "r"(addr));
            }
#pragma unroll
            for (int jj = 0; jj < 2; jj++) {
                const uint32_t addr = Bbase + (b_base + jj * 320 + ks * 8) * 4;
                asm volatile(
                    "ldmatrix.sync.aligned.m8n8.x4.shared.b16 "
                    "{%0, %1, %2, %3}, [%4];"
                    : "=r"(bf_[2 * jj][0]), "=r"(bf_[2 * jj][1]),
                      "=r"(bf_[2 * jj + 1][0]), "=r"(bf_[2 * jj + 1][1])
                    : "r"(addr));
            }
#pragma unroll
            for (int i = 0; i < 4; i++)
#pragma unroll
                for (int j = 0; j < 4; j++)
                    asm volatile(
                        "mma.sync.aligned.m16n8k16.row.col.f32.bf16.bf16.f32 "
                        "{%0,%1,%2,%3}, {%4,%5,%6,%7}, {%8,%9}, {%0,%1,%2,%3};"
                        : "+f"(c[i][j][0]), "+f"(c[i][j][1]),
                          "+f"(c[i][j][2]), "+f"(c[i][j][3])
                        : "r"(a[i][0]), "r"(a[i][1]), "r"(a[i][2]),
                          "r"(a[i][3]), "r"(bf_[j][0]), "r"(bf_[j][1]));
        }
    }
#undef ISSUE_TILE
    __syncthreads();  // all reads of sm done before epilogue reuses it

    if (TRANS_OUT) {
        // C[m,n] -> KT[b][n][s] in bf16, staged through shared
        __nv_bfloat16* Cb = (__nv_bfloat16*)Cv;
        const int b = m0 >> 11;  // / NT
        const int s0 = m0 & (NT - 1);
        float* stg = (float*)sm;  // [64][136] floats = 34816B < 61440B
#pragma unroll
        for (int p = 0; p < 2; p++) {
            __syncthreads();
            if ((warp >> 2) == p) {
#pragma unroll
                for (int i = 0; i < 4; i++)
#pragma unroll
                    for (int j = 0; j < 4; j++)
#pragma unroll
                        for (int r = 0; r < 4; r++) {
                            int row = wm + i * 16 + q + (r >> 1) * 8;
                            int col = wn + j * 8 + 2 * t4 + (r & 1) - p * 64;
                            stg[col * 136 + row] = c[i][j][r];
                        }
            }
            __syncthreads();
            const int nn = tid >> 2, ch = tid & 3;
            __nv_bfloat16* dst =
                Cb + ((size_t)(b * NV + n0 + p * 64 + nn)) * NT + s0 + ch * 32;
            const float* srow = stg + nn * 136 + ch * 32;
#pragma unroll
            for (int w = 0; w < 4; w++) {
                uint32_t pk[4];
#pragma unroll
                for (int j = 0; j < 2; j++) {
                    float4 f4 = *(const float4*)(srow + w * 8 + j * 4);
                    __nv_bfloat162 h0 = __floats2bfloat162_rn(f4.x, f4.y);
                    __nv_bfloat162 h1 = __floats2bfloat162_rn(f4.z, f4.w);
                    pk[2 * j] = *(uint32_t*)&h0;
                    pk[2 * j + 1] = *(uint32_t*)&h1;
                }
                *(uint4*)(dst + w * 8) = make_uint4(pk[0], pk[1], pk[2], pk[3]);
            }
        }
    } else {
        float* Cb = (float*)Cv + (size_t)m0 * NV + n0;
#pragma unroll
        for (int i = 0; i < 4; i++)
#pragma unroll
            for (int j = 0; j < 4; j++) {
                const int row = wm + i * 16 + q;
                const int col = wn + j * 8 + 2 * t4;
                float2 v0 = make_float2(c[i][j][0], c[i][j][1]);
                float2 v1 = make_float2(c[i][j][2], c[i][j][3]);
                *(float2*)&Cb[(size_t)row * NV + col] = v0;
                *(float2*)&Cb[(size_t)(row + 8) * NV + col] = v1;
            }
    }
}

// ---------------------------------------------------------------------------
extern "C" void kernel_launch(void* const* d_in, const int* in_sizes, int n_in,
                              void* d_out, int out_size) {
    const int* idx = (const int*)d_in[0];     // (B,T) int32
    const float* pt = (const float*)d_in[1];  // (T,1) f32
    const float* Wq = (const float*)d_in[2];  // (V,V) f32
    const float* Wv = (const float*)d_in[3];  // (V,V) f32
    float* out = (float*)d_out;               // (B,T,V) f32

    __nv_bfloat16 *pA = nullptr, *pKT = nullptr, *pWqT = nullptr, *pWvR = nullptr;
    unsigned short* pPos = nullptr;
    int *pOff = nullptr, *pCnt = nullptr, *pOff2 = nullptr;
    cudaGetSymbolAddress((void**)&pA, g_A);
    cudaGetSymbolAddress((void**)&pKT, g_KT);
    cudaGetSymbolAddress((void**)&pWqT, g_WqT);
    cudaGetSymbolAddress((void**)&pWvR, g_WvR);
    cudaGetSymbolAddress((void**)&pPos, g_pos);
    cudaGetSymbolAddress((void**)&pOff, g_off);
    cudaGetSymbolAddress((void**)&pCnt, g_cnt);
    cudaGetSymbolAddress((void**)&pOff2, g_off2);

    cudaFuncSetAttribute(gemm_bf16<true>,
                         cudaFuncAttributeMaxDynamicSharedMemorySize, GSMEM);
    cudaFuncSetAttribute(gemm_bf16<false>,
                         cudaFuncAttributeMaxDynamicSharedMemorySize, GSMEM);

    dim3 gridGemm(NV / BN, (NB * NT) / BM);  // (4, 256)

    // 0) weights to bf16 (WqT = Wq^T)
    k_wqt<<<dim3(16, 16), dim3(32, 8)>>>(Wq, pWqT);
    k_wv<<<(NV * NV) / 1024, 256>>>(Wv, pWvR);
    // 1) CSR of token positions per batch (parallel: hist -> scan -> fill)
    k_hist<<<dim3(NCH, NB), 512>>>(idx, pCnt);
    k_scan<<<NB, 512>>>(pCnt, pOff, pOff2);
    k_fill<<<dim3(NCH, NB), 512>>>(idx, pOff2, pPos);
    // 2) L1 scatter (atomic-free via CSR, float4 pt bursts), bf16 out
    k_build_l1<<<dim3(NT / 32, NB), 512>>>(pPos, pOff, pt, pA);
    // 3) K = L1 @ Wq -> KT[b][n][s] bf16
    gemm_bf16<true><<<gridGemm, 256, GSMEM>>>(pA, pWqT, (void*)pKT);
    // 4) S scatter grouped by q (atomic-free, single pass), bf16 out
    k_scatter_q<<<dim3(NV, NB), 512>>>(pPos, pOff, pKT, pA);
    // 5) logits = S @ Wv^T, fp32 out
    gemm_bf16<false><<<gridGemm, 256, GSMEM>>>(pA, pWvR, (void*)out);
}

// round 15
// speedup vs baseline: 1.3452x; 1.1011x over previous
#include <cuda_runtime.h>
#include <cuda_bf16.h>
#include <cstdint>

#define NB 16
#define NT 2048
#define NV 512
#define BM 128
#define BN 128
#define BK 64    // bf16 elements per k-tile
#define NCH 16
#define CHW (NT / NCH)  // 128
#define QG 4

// Scratch (allocation-free rule: __device__ globals).
__device__ __nv_bfloat16 g_A[(size_t)NB * NT * NV];   // L1, then reused as S
__device__ __nv_bfloat16 g_KT[(size_t)NB * NV * NT];  // K^T per batch (bf16)
__device__ __nv_bfloat16 g_WqT[NV * NV];              // Wq^T in bf16, [n][k]
__device__ __nv_bfloat16 g_WvR[NV * NV];              // Wv in bf16, [n][k]
__device__ unsigned short g_pos[NB * NT];             // CSR positions (sorted)
__device__ int g_off[NB * (NV + 1)];                  // CSR offsets
__device__ int g_cnt[NB * NCH * NV];                  // per-chunk counts
__device__ int g_off2[NB * NCH * NV];                 // per-chunk start offsets

__device__ __forceinline__ uint32_t smem_u32(const void* p) {
    return (uint32_t)__cvta_generic_to_shared(p);
}

// ---------------------------------------------------------------------------
// Fused weight prep: z=0 -> WqT = bf16(Wq^T); z=1 -> WvR = bf16(Wv)
// ---------------------------------------------------------------------------
__global__ void k_prep(const float* __restrict__ Wq, const float* __restrict__ Wv,
                       __nv_bfloat16* __restrict__ WT, __nv_bfloat16* __restrict__ WvR) {
    if (blockIdx.z == 0) {
        __shared__ float t[32][33];
        int x = blockIdx.x * 32 + threadIdx.x;
        int y = blockIdx.y * 32 + threadIdx.y;
#pragma unroll
        for (int j = 0; j < 32; j += 8)
            t[threadIdx.y + j][threadIdx.x] = Wq[(size_t)(y + j) * NV + x];
        __syncthreads();
        x = blockIdx.y * 32 + threadIdx.x;
        y = blockIdx.x * 32 + threadIdx.y;
#pragma unroll
        for (int j = 0; j < 32; j += 8)
            WT[(size_t)(y + j) * NV + x] =
                __float2bfloat16(t[threadIdx.x][threadIdx.y + j]);
    } else {
        const int blk = blockIdx.y * 16 + blockIdx.x;
        const int t = threadIdx.y * 32 + threadIdx.x;
        const int i4 = (blk * 256 + t) * 4;
        float4 v = *(const float4*)(Wv + i4);
        __nv_bfloat162* d2 = (__nv_bfloat162*)(WvR + i4);
        d2[0] = __floats2bfloat162_rn(v.x, v.y);
        d2[1] = __floats2bfloat162_rn(v.z, v.w);
    }
}

// ---------------------------------------------------------------------------
// Parallel CSR build: hist (per 128-token chunk) -> scan -> fill
// ---------------------------------------------------------------------------
__global__ void k_hist(const int* __restrict__ idx, int* __restrict__ cnt) {
    const int c = blockIdx.x, b = blockIdx.y, v = threadIdx.x;
    __shared__ int sidx[CHW];
    if (v < CHW) sidx[v] = idx[b * NT + c * CHW + v];
    __syncthreads();
    int n = 0;
#pragma unroll 8
    for (int r = 0; r < CHW; r++) n += (sidx[r] == v);
    cnt[(b * NCH + c) * NV + v] = n;
}

__global__ void k_scan(const int* __restrict__ cnt, int* __restrict__ off,
                       int* __restrict__ off2) {
    const int b = blockIdx.x, v = threadIdx.x;
    __shared__ int wsum[16];
    int c[NCH];
    int tot = 0;
#pragma unroll
    for (int j = 0; j < NCH; j++) {
        c[j] = cnt[(b * NCH + j) * NV + v];
        tot += c[j];
    }
    const int lane = v & 31, w = v >> 5;
    int incl = tot;
#pragma unroll
    for (int d = 1; d < 32; d <<= 1) {
        int x = __shfl_up_sync(0xffffffffu, incl, d);
        if (lane >= d) incl += x;
    }
    if (lane == 31) wsum[w] = incl;
    __syncthreads();
    if (w == 0) {
        int s = (lane < 16) ? wsum[lane] : 0;
#pragma unroll
        for (int d = 1; d < 16; d <<= 1) {
            int x = __shfl_up_sync(0xffffffffu, s, d);
            if (lane >= d) s += x;
        }
        if (lane < 16) wsum[lane] = s;
    }
    __syncthreads();
    int o = incl - tot + (w ? wsum[w - 1] : 0);  // exclusive prefix
    off[b * (NV + 1) + v] = o;
    if (v == NV - 1) off[b * (NV + 1) + NV] = NT;
#pragma unroll
    for (int j = 0; j < NCH; j++) {
        off2[(b * NCH + j) * NV + v] = o;
        o += c[j];
    }
}

__global__ void k_fill(const int* __restrict__ idx, const int* __restrict__ off2,
                       unsigned short* __restrict__ pos) {
    const int c = blockIdx.x, b = blockIdx.y, v = threadIdx.x;
    __shared__ int sidx[CHW];
    if (v < CHW) sidx[v] = idx[b * NT + c * CHW + v];
    __syncthreads();
    int o = off2[(b * NCH + c) * NV + v];
    for (int r = 0; r < CHW; r++)
        if (sidx[r] == v) pos[b * NT + (o++)] = (unsigned short)(c * CHW + r);
}

// ---------------------------------------------------------------------------
// L1[b,s,v] = sum_{r<=s, idx[b,r]==v} pt[s-r], atomic-free via CSR.
// 512 threads, 1 vocab per thread. pt staged as 4 shifted copies so the
// 32-add burst uses 8x LDS.128.  (R14 version, measured good.)
// ---------------------------------------------------------------------------
__global__ void __launch_bounds__(512)
k_build_l1(const unsigned short* __restrict__ pos, const int* __restrict__ off,
           const float* __restrict__ pt, __nv_bfloat16* __restrict__ L1) {
    const int s0 = blockIdx.x * 32, b = blockIdx.y;
    const int v = threadIdx.x;
    const int smax = s0 + 31;
    __shared__ __align__(16) float ptc[4][NT];
    __shared__ unsigned short psh[NT];
    for (int f = v; f <= smax; f += 512) {
        ptc[0][f] = pt[f];
        ptc[1][f] = pt[f + 1 < NT ? f + 1 : NT - 1];
        ptc[2][f] = pt[f + 2 < NT ? f + 2 : NT - 1];
        ptc[3][f] = pt[f + 3 < NT ? f + 3 : NT - 1];
    }
    for (int d = v; d < NT; d += 512) psh[d] = pos[b * NT + d];
    __syncthreads();
    float acc[32];
#pragma unroll
    for (int i = 0; i < 32; i++) acc[i] = 0.f;
    const int e0 = off[b * (NV + 1) + v], e1 = off[b * (NV + 1) + v + 1];
    for (int e = e0; e < e1; e++) {
        const int r = psh[e];
        if (r > smax) break;
        const int d = s0 - r;
        if (d >= 0) {
            const int a = d & 3;
            const float4* p4 = (const float4*)&ptc[a][d - a];
#pragma unroll
            for (int k = 0; k < 8; k++) {
                float4 q4 = p4[k];
                acc[4 * k + 0] += q4.x;
                acc[4 * k + 1] += q4.y;
                acc[4 * k + 2] += q4.z;
                acc[4 * k + 3] += q4.w;
            }
        } else {
#pragma unroll
            for (int i = 0; i < 32; i++)
                if (s0 + i >= r) acc[i] += ptc[0][s0 + i - r];
        }
    }
#pragma unroll
    for (int i = 0; i < 32; i++)
        L1[((size_t)(b * NT + s0 + i)) * NV + v] = __float2bfloat16(acc[i]);
}

// ---------------------------------------------------------------------------
// S-scatter grouped by query token, QG=4 q's per block: psh staging, barrier
// and block overhead amortized 4x. Walk work is invariant to grouping.
// ---------------------------------------------------------------------------
__global__ void __launch_bounds__(512)
k_scatter_q(const unsigned short* __restrict__ pos, const int* __restrict__ off,
            const __nv_bfloat16* __restrict__ KT, __nv_bfloat16* __restrict__ S) {
    const int qg = blockIdx.x, b = blockIdx.y;
    const int v = threadIdx.x;
    __shared__ __align__(16) __nv_bfloat16 colsh[QG][NT];
    __shared__ unsigned short psh[NT];
    __shared__ int eqs[QG + 1];
    __shared__ int tlsh[QG];

    if (v <= QG) eqs[v] = off[b * (NV + 1) + qg * QG + v];
    __syncthreads();
    const unsigned short* pb = pos + b * NT;
    if (v < QG) tlsh[v] = (eqs[v + 1] > eqs[v]) ? (int)pb[eqs[v + 1] - 1] : -1;
    for (int d = v; d < NT; d += 512) psh[d] = pb[d];
    __syncthreads();

    // stage up to QG K-columns (bf16, contiguous KT rows) via cp.async
#pragma unroll
    for (int j = 0; j < QG; j++) {
        const int tl = tlsh[j];
        if (tl < 0) continue;
        const __nv_bfloat16* src = KT + ((size_t)(b * NV + qg * QG + j)) * NT;
        for (int c8 = v; c8 * 8 <= tl; c8 += 512) {
            uint32_t dst = smem_u32(&colsh[j][c8 * 8]);
            asm volatile("cp.async.cg.shared.global [%0], [%1], 16;" ::"r"(dst),
                         "l"(src + c8 * 8));
        }
    }
    asm volatile("cp.async.commit_group;");
    asm volatile("cp.async.wait_group 0;");
    __syncthreads();

    const int e0 = off[b * (NV + 1) + v];
    const int e1 = off[b * (NV + 1) + v + 1];
    __nv_bfloat16* Sb = S + (size_t)b * NT * NV + v;
#pragma unroll 1
    for (int j = 0; j < QG; j++) {
        const int lenT = eqs[j + 1] - eqs[j];
        if (lenT == 0) continue;
        int e = e0;
        float acc = 0.f;
        for (int jj = 0; jj < lenT; jj++) {
            const int t = psh[eqs[j] + jj];
            while (e < e1 && psh[e] <= t) {
                acc += __bfloat162float(colsh[j][psh[e]]);
                e++;
            }
            Sb[(size_t)t * NV] = __float2bfloat16(acc);
        }
    }
}

// ---------------------------------------------------------------------------
// bf16 GEMM, CTA 128x128, BK=64 (bf16), 8 warps of 64x32 each, 3-stage
// cp.async pipeline (8 k-iterations, 1 barrier each), stride-36-u32 padded
// smem (conflict-free ldmatrix), ldmatrix fragment loads.
// B row-major [n][k]. C[m,n] = sum_k A[m,k]*B[n,k].
//   TRANS_OUT=true : C[m,n] -> KT[b][n][s] (bf16) via shared-staged transpose
//   TRANS_OUT=false: row-major fp32 out
// ---------------------------------------------------------------------------
#define TILE_U32 4608              // 128 rows * 36 u32
#define GSMEM 110592               // 3 stages * 2 tiles * 4608 u32 * 4B

template <bool TRANS_OUT>
__global__ void __launch_bounds__(256, 2)
gemm_bf16(const __nv_bfloat16* __restrict__ A,
          const __nv_bfloat16* __restrict__ Bsrc, void* __restrict__ Cv) {
    extern __shared__ __align__(16) uint32_t sm[];  // 27648 u32 = 108KB
    uint32_t* Asm = sm;                 // [3][128][36] u32 (32 data + 4 pad)
    uint32_t* Bsm = sm + 3 * TILE_U32;  // [3][128][36]

    const int tid = threadIdx.x;
    const int lane = tid & 31, warp = tid >> 5;
    const int wm = (warp & 1) * 64, wn = (warp >> 1) * 32;
    const int q = lane >> 2, t4 = lane & 3;
    const int m0 = blockIdx.y * BM, n0 = blockIdx.x * BN;

    // ldmatrix per-lane address offsets (u32 units, within one buffer)
    const int g = lane >> 3, lr = lane & 7;
    const int a_base = (wm + (g & 1) * 8 + lr) * 36 + (g >> 1) * 4;
    const int b_base = (wn + (g >> 1) * 8 + lr) * 36 + (g & 1) * 4;

    float c[4][4][4];
#pragma unroll
    for (int i = 0; i < 4; i++)
#pragma unroll
        for (int j = 0; j < 4; j++)
#pragma unroll
            for (int r = 0; r < 4; r++) c[i][j][r] = 0.f;

#define ISSUE_TILE(KT_, BUF_)                                                  \
    do {                                                                       \
        _Pragma("unroll") for (int i_ = 0; i_ < 4; i_++) {                     \
            int f = tid + i_ * 256;                                            \
            int m_ = f >> 3, k8 = f & 7;                                       \
            const __nv_bfloat16* src =                                         \
                A + (size_t)(m0 + m_) * NV + (KT_) + k8 * 8;                   \
            uint32_t dst =                                                     \
                smem_u32(&Asm[(BUF_)*TILE_U32 + m_ * 36 + k8 * 4]);            \
            asm volatile("cp.async.cg.shared.global [%0], [%1], 16;" ::"r"(    \
                             dst),                                             \
                         "l"(src));                                            \
        }                                                                      \
        _Pragma("unroll") for (int i_ = 0; i_ < 4; i_++) {                     \
            int f = tid + i_ * 256;                                            \
            int n_ = f >> 3, k8 = f & 7;                                       \
            const __nv_bfloat16* src =                                         \
                Bsrc + (size_t)(n0 + n_) * NV + (KT_) + k8 * 8;                \
            uint32_t dst =                                                     \
                smem_u32(&Bsm[(BUF_)*TILE_U32 + n_ * 36 + k8 * 4]);            \
            asm volatile("cp.async.cg.shared.global [%0], [%1], 16;" ::"r"(    \
                             dst),                                             \
                         "l"(src));                                            \
        }                                                                      \
        asm volatile("cp.async.commit_group;");                                \
    } while (0)

    // prologue: 2 tiles in flight
    ISSUE_TILE(0, 0);
    ISSUE_TILE(BK, 1);
    const int NKT = NV / BK;  // 8
#pragma unroll 1
    for (int it = 0; it < NKT; it++) {
        if (it + 1 < NKT) {
            asm volatile("cp.async.wait_group 1;");
        } else {
            asm volatile("cp.async.wait_group 0;");
        }
        __syncthreads();
        // issue tile it+2 into buf (it+2)%3 == (it-1)%3; all reads of that
        // buffer finished in iteration it-1, fenced by the barrier above.
        if (it + 2 < NKT) ISSUE_TILE((it + 2) * BK, (it + 2) % 3);

        const int buf = it % 3;
        const uint32_t Abase = smem_u32(&Asm[buf * TILE_U32]);
        const uint32_t Bbase = smem_u32(&Bsm[buf * TILE_U32]);
#pragma unroll
        for (int ks = 0; ks < 4; ks++) {
            uint32_t a[4][4], bf_[4][2];
#pragma unroll
            for (int i = 0; i < 4; i++) {
                const uint32_t addr = Abase + (a_base + i * 576 + ks * 8) * 4;
                asm volatile(
                    "ldmatrix.sync.aligned.m8n8.x4.shared.b16 "
                    "{%0, %1, %2, %3}, [%4];"
                    : "=r"(a[i][0]), "=r"(a[i][1]), "=r"(a[i][2]), "=r"(a[i][3])
                    : "r"(addr));
            }
#pragma unroll
            for (int jj = 0; jj < 2; jj++) {
                const uint32_t addr = Bbase + (b_base + jj * 576 + ks * 8) * 4;
                asm volatile(
                    "ldmatrix.sync.aligned.m8n8.x4.shared.b16 "
                    "{%0, %1, %2, %3}, [%4];"
                    : "=r"(bf_[2 * jj][0]), "=r"(bf_[2 * jj][1]),
                      "=r"(bf_[2 * jj + 1][0]), "=r"(bf_[2 * jj + 1][1])
                    : "r"(addr));
            }
#pragma unroll
            for (int i = 0; i < 4; i++)
#pragma unroll
                for (int j = 0; j < 4; j++)
                    asm volatile(
                        "mma.sync.aligned.m16n8k16.row.col.f32.bf16.bf16.f32 "
                        "{%0,%1,%2,%3}, {%4,%5,%6,%7}, {%8,%9}, {%0,%1,%2,%3};"
                        : "+f"(c[i][j][0]), "+f"(c[i][j][1]),
                          "+f"(c[i][j][2]), "+f"(c[i][j][3])
                        : "r"(a[i][0]), "r"(a[i][1]), "r"(a[i][2]),
                          "r"(a[i][3]), "r"(bf_[j][0]), "r"(bf_[j][1]));
        }
    }
#undef ISSUE_TILE
    __syncthreads();  // all reads of sm done before epilogue reuses it

    if (TRANS_OUT) {
        // C[m,n] -> KT[b][n][s] in bf16, staged through shared
        __nv_bfloat16* Cb = (__nv_bfloat16*)Cv;
        const int b = m0 >> 11;  // / NT
        const int s0 = m0 & (NT - 1);
        float* stg = (float*)sm;  // [64][136] floats = 34816B < GSMEM
#pragma unroll
        for (int p = 0; p < 2; p++) {
            __syncthreads();
            if ((warp >> 2) == p) {
#pragma unroll
                for (int i = 0; i < 4; i++)
#pragma unroll
                    for (int j = 0; j < 4; j++)
#pragma unroll
                        for (int r = 0; r < 4; r++) {
                            int row = wm + i * 16 + q + (r >> 1) * 8;
                            int col = wn + j * 8 + 2 * t4 + (r & 1) - p * 64;
                            stg[col * 136 + row] = c[i][j][r];
                        }
            }
            __syncthreads();
            const int nn = tid >> 2, ch = tid & 3;
            __nv_bfloat16* dst =
                Cb + ((size_t)(b * NV + n0 + p * 64 + nn)) * NT + s0 + ch * 32;
            const float* srow = stg + nn * 136 + ch * 32;
#pragma unroll
            for (int w = 0; w < 4; w++) {
                uint32_t pk[4];
#pragma unroll
                for (int j = 0; j < 2; j++) {
                    float4 f4 = *(const float4*)(srow + w * 8 + j * 4);
                    __nv_bfloat162 h0 = __floats2bfloat162_rn(f4.x, f4.y);
                    __nv_bfloat162 h1 = __floats2bfloat162_rn(f4.z, f4.w);
                    pk[2 * j] = *(uint32_t*)&h0;
                    pk[2 * j + 1] = *(uint32_t*)&h1;
                }
                *(uint4*)(dst + w * 8) = make_uint4(pk[0], pk[1], pk[2], pk[3]);
            }
        }
    } else {
        float* Cb = (float*)Cv + (size_t)m0 * NV + n0;
#pragma unroll
        for (int i = 0; i < 4; i++)
#pragma unroll
            for (int j = 0; j < 4; j++) {
                const int row = wm + i * 16 + q;
                const int col = wn + j * 8 + 2 * t4;
                float2 v0 = make_float2(c[i][j][0], c[i][j][1]);
                float2 v1 = make_float2(c[i][j][2], c[i][j][3]);
                *(float2*)&Cb[(size_t)row * NV + col] = v0;
                *(float2*)&Cb[(size_t)(row + 8) * NV + col] = v1;
            }
    }
}

// ---------------------------------------------------------------------------
extern "C" void kernel_launch(void* const* d_in, const int* in_sizes, int n_in,
                              void* d_out, int out_size) {
    const int* idx = (const int*)d_in[0];     // (B,T) int32
    const float* pt = (const float*)d_in[1];  // (T,1) f32
    const float* Wq = (const float*)d_in[2];  // (V,V) f32
    const float* Wv = (const float*)d_in[3];  // (V,V) f32
    float* out = (float*)d_out;               // (B,T,V) f32

    __nv_bfloat16 *pA = nullptr, *pKT = nullptr, *pWqT = nullptr, *pWvR = nullptr;
    unsigned short* pPos = nullptr;
    int *pOff = nullptr, *pCnt = nullptr, *pOff2 = nullptr;
    cudaGetSymbolAddress((void**)&pA, g_A);
    cudaGetSymbolAddress((void**)&pKT, g_KT);
    cudaGetSymbolAddress((void**)&pWqT, g_WqT);
    cudaGetSymbolAddress((void**)&pWvR, g_WvR);
    cudaGetSymbolAddress((void**)&pPos, g_pos);
    cudaGetSymbolAddress((void**)&pOff, g_off);
    cudaGetSymbolAddress((void**)&pCnt, g_cnt);
    cudaGetSymbolAddress((void**)&pOff2, g_off2);

    cudaFuncSetAttribute(gemm_bf16<true>,
                         cudaFuncAttributeMaxDynamicSharedMemorySize, GSMEM);
    cudaFuncSetAttribute(gemm_bf16<false>,
                         cudaFuncAttributeMaxDynamicSharedMemorySize, GSMEM);

    dim3 gridGemm(NV / BN, (NB * NT) / BM);  // (4, 256)

    // 0) fused weight prep (WqT = bf16(Wq^T), WvR = bf16(Wv))
    k_prep<<<dim3(16, 16, 2), dim3(32, 8)>>>(Wq, Wv, pWqT, pWvR);
    // 1) CSR of token positions per batch (parallel: hist -> scan -> fill)
    k_hist<<<dim3(NCH, NB), 512>>>(idx, pCnt);
    k_scan<<<NB, 512>>>(pCnt, pOff, pOff2);
    k_fill<<<dim3(NCH, NB), 512>>>(idx, pOff2, pPos);
    // 2) L1 scatter (atomic-free via CSR, float4 pt bursts), bf16 out
    k_build_l1<<<dim3(NT / 32, NB), 512>>>(pPos, pOff, pt, pA);
    // 3) K = L1 @ Wq -> KT[b][n][s] bf16
    gemm_bf16<true><<<gridGemm, 256, GSMEM>>>(pA, pWqT, (void*)pKT);
    // 4) S scatter, 4 q's per block (atomic-free, single pass), bf16 out
    k_scatter_q<<<dim3(NV / QG, NB), 512>>>(pPos, pOff, pKT, pA);
    // 5) logits = S @ Wv^T, fp32 out
    gemm_bf16<false><<<gridGemm, 256, GSMEM>>>(pA, pWvR, (void*)out);
}